// round 2
// baseline (speedup 1.0000x reference)
#include <cuda_runtime.h>
#include <math.h>

#define TT 512
#define BB 32
#define II 512
#define HH 1024
#define G3 3072
#define NCTA 128
#define NTHR 192
#define OUT_COPY (TT * BB * HH)

// -------- scratch (static device allocations are the sanctioned workaround) --------
__device__ float g_gi[(size_t)TT * BB * G3];   // 201 MB: gi = X@w_ih + b_ih
__device__ float g_wT[G3 * HH];                // w_hh transposed: [3H][H]
__device__ float g_h[2][HH * BB];              // ping-pong hidden state, layout [k][b]
__device__ unsigned g_bar_count = 0;
__device__ volatile unsigned g_bar_phase = 0;

// ============================================================
// Transpose w_hh [H][3H] -> g_wT [3H][H]
// ============================================================
__global__ void k_transpose(const float* __restrict__ whh) {
    __shared__ float tile[32][33];
    const int col0 = blockIdx.x * 32;  // 3H dim
    const int row0 = blockIdx.y * 32;  // H dim
    const int tx = threadIdx.x, ty = threadIdx.y;
#pragma unroll
    for (int r = ty; r < 32; r += 8)
        tile[r][tx] = whh[(row0 + r) * G3 + col0 + tx];
    __syncthreads();
#pragma unroll
    for (int r = ty; r < 32; r += 8)
        g_wT[(size_t)(col0 + r) * HH + row0 + tx] = tile[tx][r];
}

// ============================================================
// Input GEMM: gi[m][n] = sum_k X[m][k]*W[k][n] + bias[n]
// M=16384, K=512, N=3072.  BM=128, BN=64, BK=8, TM=8, TN=4, 256 thr
// ============================================================
__global__ __launch_bounds__(256) void k_gemm_gi(const float* __restrict__ X,
                                                 const float* __restrict__ W,
                                                 const float* __restrict__ bias) {
    __shared__ float a_s[8][128];
    __shared__ float b_s[8][64];
    const int bm = blockIdx.y * 128;
    const int bn = blockIdx.x * 64;
    const int tid = threadIdx.x;
    const int tx = tid & 15;   // 0..15  -> 4 cols each
    const int ty = tid >> 4;   // 0..15  -> 8 rows each

    const int arow = tid >> 1;         // 0..127
    const int ak   = (tid & 1) * 4;    // 0 or 4
    const int bk   = tid >> 5;         // 0..7
    const int bnc  = (tid & 31) * 2;   // 0..62

    float acc[8][4];
#pragma unroll
    for (int i = 0; i < 8; i++)
#pragma unroll
        for (int j = 0; j < 4; j++) acc[i][j] = 0.f;

    const float* Xp = X + (size_t)(bm + arow) * II + ak;
    const float* Wp = W + (size_t)bk * G3 + bn + bnc;

    for (int k0 = 0; k0 < II; k0 += 8) {
        float4 av = *(const float4*)(Xp + k0);
        float2 bv = *(const float2*)(Wp + (size_t)k0 * G3);
        a_s[ak + 0][arow] = av.x;
        a_s[ak + 1][arow] = av.y;
        a_s[ak + 2][arow] = av.z;
        a_s[ak + 3][arow] = av.w;
        *(float2*)&b_s[bk][bnc] = bv;
        __syncthreads();
#pragma unroll
        for (int kk = 0; kk < 8; kk++) {
            float4 a0 = *(const float4*)&a_s[kk][ty * 8];
            float4 a1 = *(const float4*)&a_s[kk][ty * 8 + 4];
            float4 b0 = *(const float4*)&b_s[kk][tx * 4];
            float ar[8] = {a0.x, a0.y, a0.z, a0.w, a1.x, a1.y, a1.z, a1.w};
            float br[4] = {b0.x, b0.y, b0.z, b0.w};
#pragma unroll
            for (int i = 0; i < 8; i++)
#pragma unroll
                for (int j = 0; j < 4; j++) acc[i][j] = fmaf(ar[i], br[j], acc[i][j]);
        }
        __syncthreads();
    }
    float4 bvv = *(const float4*)(bias + bn + tx * 4);
#pragma unroll
    for (int i = 0; i < 8; i++) {
        const size_t row = (size_t)(bm + ty * 8 + i);
        float4 o;
        o.x = acc[i][0] + bvv.x;
        o.y = acc[i][1] + bvv.y;
        o.z = acc[i][2] + bvv.z;
        o.w = acc[i][3] + bvv.w;
        *(float4*)&g_gi[row * G3 + bn + tx * 4] = o;
    }
}

// ============================================================
// Grid-wide barrier (all NCTA CTAs are wave-1 resident: 1 CTA/SM by smem)
// Callers must __threadfence() their own global stores before calling.
// ============================================================
__device__ __forceinline__ void grid_bar(unsigned& phase) {
    __syncthreads();
    if (threadIdx.x == 0) {
        unsigned old = atomicAdd(&g_bar_count, 1u);
        if (old == NCTA - 1) {
            g_bar_count = 0;
            __threadfence();
            g_bar_phase = phase + 1;
        } else {
            while (g_bar_phase == phase) { }
        }
        __threadfence();
    }
    __syncthreads();
    phase++;
}

// ============================================================
// Persistent GRU recurrence.
// 128 CTAs x 192 threads. CTA c owns hidden dims k in [8c, 8c+8).
// GEMM thread map: cl = tid%24 (gate*8+kl), bg = tid/24 (4 batches each).
// ============================================================
__global__ __launch_bounds__(NTHR, 1) void k_gru(const float* __restrict__ paddings,
                                                 const float* __restrict__ b_hh,
                                                 float* __restrict__ out,
                                                 int copies) {
    extern __shared__ float smem[];
    float* h_s = smem;                       // [1024][32]
    float* gh_s = smem + HH * BB;            // [24][32]
    float4* hs4 = (float4*)h_s;

    const int tid = threadIdx.x;
    const int c = blockIdx.x;
    const int cl = tid % 24;     // 0..23 : gate*8 + kl
    const int bg = tid / 24;     // 0..7  : batches 4*bg..4*bg+3
    const int gate = cl >> 3;
    const int klq = cl & 7;
    const int col = gate * HH + c * 8 + klq;         // global column in 3H
    const float4* wp4 = (const float4*)(g_wT + (size_t)col * HH);

    // gate-phase item indices (256 (kl,b) pairs over 192 threads)
    const int i0 = tid;
    const int i1 = tid + NTHR;
    const int kl0 = i0 & 7, b0 = i0 >> 3, k0 = c * 8 + kl0;
    const int kl1 = i1 & 7, b1 = i1 >> 3, k1 = c * 8 + kl1;
    const bool has1 = (i1 < 256);

    // hoist b_hh (constant over time)
    const float bh_r0 = b_hh[k0], bh_z0 = b_hh[HH + k0], bh_n0 = b_hh[2 * HH + k0];
    float bh_r1 = 0.f, bh_z1 = 0.f, bh_n1 = 0.f;
    if (has1) { bh_r1 = b_hh[k1]; bh_z1 = b_hh[HH + k1]; bh_n1 = b_hh[2 * HH + k1]; }

    unsigned phase = g_bar_phase;

    // zero h buffer 0 (rows owned by this CTA)
    for (int idx = tid; idx < 8 * BB; idx += NTHR)
        __stcg(&g_h[0][c * 8 * BB + idx], 0.f);
    __threadfence();
    grid_bar(phase);

    for (int t = 0; t < TT; t++) {
        // ---- prefetch gi / paddings for the gate phase (independent of GEMM) ----
        const float* gib = g_gi + (size_t)t * BB * G3;
        const float gi_r0 = __ldg(gib + (size_t)b0 * G3 + k0);
        const float gi_z0 = __ldg(gib + (size_t)b0 * G3 + HH + k0);
        const float gi_n0 = __ldg(gib + (size_t)b0 * G3 + 2 * HH + k0);
        const float p0 = __ldg(paddings + t * BB + b0);
        float gi_r1 = 0.f, gi_z1 = 0.f, gi_n1 = 0.f, p1 = 0.f;
        if (has1) {
            gi_r1 = __ldg(gib + (size_t)b1 * G3 + k1);
            gi_z1 = __ldg(gib + (size_t)b1 * G3 + HH + k1);
            gi_n1 = __ldg(gib + (size_t)b1 * G3 + 2 * HH + k1);
            p1 = __ldg(paddings + t * BB + b1);
        }

        // ---- load h (prev step) into shared: [k][b] ----
        const float4* hb = (const float4*)g_h[t & 1];
        for (int idx = tid; idx < (HH * BB) / 4; idx += NTHR)
            hs4[idx] = __ldcg(hb + idx);
        __syncthreads();

        // ---- gh = h @ w_hh  (this CTA's 24 columns, 32 batches) ----
        float acc0 = 0.f, acc1 = 0.f, acc2 = 0.f, acc3 = 0.f;
#pragma unroll 4
        for (int kq = 0; kq < HH / 4; kq++) {
            const float4 wv = __ldg(wp4 + kq);
            const float4 h0 = hs4[(kq * 4 + 0) * 8 + bg];
            const float4 h1 = hs4[(kq * 4 + 1) * 8 + bg];
            const float4 h2 = hs4[(kq * 4 + 2) * 8 + bg];
            const float4 h3 = hs4[(kq * 4 + 3) * 8 + bg];
            acc0 = fmaf(wv.x, h0.x, acc0); acc1 = fmaf(wv.x, h0.y, acc1);
            acc2 = fmaf(wv.x, h0.z, acc2); acc3 = fmaf(wv.x, h0.w, acc3);
            acc0 = fmaf(wv.y, h1.x, acc0); acc1 = fmaf(wv.y, h1.y, acc1);
            acc2 = fmaf(wv.y, h1.z, acc2); acc3 = fmaf(wv.y, h1.w, acc3);
            acc0 = fmaf(wv.z, h2.x, acc0); acc1 = fmaf(wv.z, h2.y, acc1);
            acc2 = fmaf(wv.z, h2.z, acc2); acc3 = fmaf(wv.z, h2.w, acc3);
            acc0 = fmaf(wv.w, h3.x, acc0); acc1 = fmaf(wv.w, h3.y, acc1);
            acc2 = fmaf(wv.w, h3.z, acc2); acc3 = fmaf(wv.w, h3.w, acc3);
        }
        gh_s[cl * 32 + bg * 4 + 0] = acc0;
        gh_s[cl * 32 + bg * 4 + 1] = acc1;
        gh_s[cl * 32 + bg * 4 + 2] = acc2;
        gh_s[cl * 32 + bg * 4 + 3] = acc3;
        __syncthreads();

        // ---- gates + state update + output ----
        {
            const float hr = gh_s[kl0 * 32 + b0] + bh_r0;
            const float hz = gh_s[(8 + kl0) * 32 + b0] + bh_z0;
            const float hn = gh_s[(16 + kl0) * 32 + b0] + bh_n0;
            const float r = 1.f / (1.f + expf(-(gi_r0 + hr)));
            const float z = 1.f / (1.f + expf(-(gi_z0 + hz)));
            const float n = tanhf(gi_n0 + r * hn);
            const float hold = h_s[k0 * 32 + b0];
            float hnew = (1.f - z) * n + z * hold;
            hnew = p0 * hold + (1.f - p0) * hnew;
            __stcg(&g_h[(t + 1) & 1][k0 * 32 + b0], hnew);
            const size_t ob = (size_t)(t * BB + b0) * HH + k0;
            for (int cp = 0; cp < copies; cp++) out[ob + (size_t)cp * OUT_COPY] = hnew;
        }
        if (has1) {
            const float hr = gh_s[kl1 * 32 + b1] + bh_r1;
            const float hz = gh_s[(8 + kl1) * 32 + b1] + bh_z1;
            const float hn = gh_s[(16 + kl1) * 32 + b1] + bh_n1;
            const float r = 1.f / (1.f + expf(-(gi_r1 + hr)));
            const float z = 1.f / (1.f + expf(-(gi_z1 + hz)));
            const float n = tanhf(gi_n1 + r * hn);
            const float hold = h_s[k1 * 32 + b1];
            float hnew = (1.f - z) * n + z * hold;
            hnew = p1 * hold + (1.f - p1) * hnew;
            __stcg(&g_h[(t + 1) & 1][k1 * 32 + b1], hnew);
            const size_t ob = (size_t)(t * BB + b1) * HH + k1;
            for (int cp = 0; cp < copies; cp++) out[ob + (size_t)cp * OUT_COPY] = hnew;
        }

        __threadfence();
        grid_bar(phase);
    }
}

// ============================================================
extern "C" void kernel_launch(void* const* d_in, const int* in_sizes, int n_in,
                              void* d_out, int out_size) {
    const float* input    = (const float*)d_in[0];
    const float* paddings = (const float*)d_in[1];
    const float* w_ih     = (const float*)d_in[2];
    const float* w_hh     = (const float*)d_in[3];
    const float* b_ih     = (const float*)d_in[4];
    const float* b_hh     = (const float*)d_in[5];
    float* out = (float*)d_out;

    int copies = out_size / OUT_COPY;
    if (copies < 1) copies = 1;
    if (copies > 2) copies = 2;

    const int smem_bytes = (HH * BB + 24 * BB) * (int)sizeof(float);  // 134144
    cudaFuncSetAttribute(k_gru, cudaFuncAttributeMaxDynamicSharedMemorySize, smem_bytes);

    k_transpose<<<dim3(G3 / 32, HH / 32), dim3(32, 8)>>>(w_hh);
    k_gemm_gi<<<dim3(G3 / 64, (TT * BB) / 128), 256>>>(input, w_ih, b_ih);
    k_gru<<<NCTA, NTHR, smem_bytes>>>(paddings, b_hh, out, copies);
}

// round 3
// speedup vs baseline: 1.8249x; 1.8249x over previous
#include <cuda_runtime.h>
#include <math.h>

#define TT 512
#define BB 32
#define II 512
#define HH 1024
#define G3 3072
#define NCTA 128
#define NTHR 192
#define OUT_COPY (TT * BB * HH)

// smem partition for k_gru (floats):
//   h_s  : [0, 32768)        h state [k][b]            131072 B
//   w4_s : [32768, 57344)    w as float4 [kq][24 cols]  98304 B
//   gh_s : [57344, 58112)    gh exchange [24][32]        3072 B
// total 58112 floats = 232448 B = exactly the 227 KB opt-in max.
#define SMEM_FLOATS 58112
#define W4_OFF 32768
#define GH_OFF 57344

// -------- static device scratch --------
__device__ float g_gi[(size_t)TT * BB * G3];   // 201 MB: gi = X@w_ih + b_ih
__device__ float g_wT[G3 * HH];                // w_hh transposed: [3H][H]
__device__ float g_h[2][HH * BB];              // ping-pong hidden state, layout [k][b]
__device__ unsigned g_bar_count = 0;
__device__ volatile unsigned g_bar_phase = 0;

// ============================================================
// Transpose w_hh [H][3H] -> g_wT [3H][H]
// ============================================================
__global__ void k_transpose(const float* __restrict__ whh) {
    __shared__ float tile[32][33];
    const int col0 = blockIdx.x * 32;  // 3H dim
    const int row0 = blockIdx.y * 32;  // H dim
    const int tx = threadIdx.x, ty = threadIdx.y;
#pragma unroll
    for (int r = ty; r < 32; r += 8)
        tile[r][tx] = whh[(row0 + r) * G3 + col0 + tx];
    __syncthreads();
#pragma unroll
    for (int r = ty; r < 32; r += 8)
        g_wT[(size_t)(col0 + r) * HH + row0 + tx] = tile[tx][r];
}

// ============================================================
// Input GEMM: gi[m][n] = sum_k X[m][k]*W[k][n] + bias[n]
// M=16384, K=512, N=3072.  BM=BN=128, BK=8, TM=TN=8, 256 thr
// ============================================================
__global__ __launch_bounds__(256) void k_gemm_gi(const float* __restrict__ X,
                                                 const float* __restrict__ W,
                                                 const float* __restrict__ bias) {
    __shared__ float a_s[8][128];
    __shared__ float b_s[8][128];
    const int bm = blockIdx.y * 128;
    const int bn = blockIdx.x * 128;
    const int tid = threadIdx.x;
    const int tx = tid & 15;   // 0..15 -> 8 cols each
    const int ty = tid >> 4;   // 0..15 -> 8 rows each

    const int arow = tid >> 1;         // 0..127
    const int ak   = (tid & 1) * 4;    // 0 or 4
    const int bk   = tid >> 5;         // 0..7
    const int bnc  = (tid & 31) * 4;   // 0..124

    float acc[8][8];
#pragma unroll
    for (int i = 0; i < 8; i++)
#pragma unroll
        for (int j = 0; j < 8; j++) acc[i][j] = 0.f;

    const float* Xp = X + (size_t)(bm + arow) * II + ak;
    const float* Wp = W + (size_t)bk * G3 + bn + bnc;

    for (int k0 = 0; k0 < II; k0 += 8) {
        float4 av = *(const float4*)(Xp + k0);
        float4 bv = *(const float4*)(Wp + (size_t)k0 * G3);
        a_s[ak + 0][arow] = av.x;
        a_s[ak + 1][arow] = av.y;
        a_s[ak + 2][arow] = av.z;
        a_s[ak + 3][arow] = av.w;
        *(float4*)&b_s[bk][bnc] = bv;
        __syncthreads();
#pragma unroll
        for (int kk = 0; kk < 8; kk++) {
            float4 a0 = *(const float4*)&a_s[kk][ty * 8];
            float4 a1 = *(const float4*)&a_s[kk][ty * 8 + 4];
            float4 b0 = *(const float4*)&b_s[kk][tx * 8];
            float4 b1 = *(const float4*)&b_s[kk][tx * 8 + 4];
            float ar[8] = {a0.x, a0.y, a0.z, a0.w, a1.x, a1.y, a1.z, a1.w};
            float br[8] = {b0.x, b0.y, b0.z, b0.w, b1.x, b1.y, b1.z, b1.w};
#pragma unroll
            for (int i = 0; i < 8; i++)
#pragma unroll
                for (int j = 0; j < 8; j++) acc[i][j] = fmaf(ar[i], br[j], acc[i][j]);
        }
        __syncthreads();
    }
    float4 bv0 = *(const float4*)(bias + bn + tx * 8);
    float4 bv1 = *(const float4*)(bias + bn + tx * 8 + 4);
#pragma unroll
    for (int i = 0; i < 8; i++) {
        const size_t row = (size_t)(bm + ty * 8 + i);
        float4 o0, o1;
        o0.x = acc[i][0] + bv0.x; o0.y = acc[i][1] + bv0.y;
        o0.z = acc[i][2] + bv0.z; o0.w = acc[i][3] + bv0.w;
        o1.x = acc[i][4] + bv1.x; o1.y = acc[i][5] + bv1.y;
        o1.z = acc[i][6] + bv1.z; o1.w = acc[i][7] + bv1.w;
        *(float4*)&g_gi[row * G3 + bn + tx * 8]     = o0;
        *(float4*)&g_gi[row * G3 + bn + tx * 8 + 4] = o1;
    }
}

// ============================================================
// Grid-wide barrier (all NCTA CTAs wave-1 resident: 1 CTA/SM by smem)
// ============================================================
__device__ __forceinline__ void grid_bar(unsigned& phase) {
    __syncthreads();
    if (threadIdx.x == 0) {
        unsigned old = atomicAdd(&g_bar_count, 1u);
        if (old == NCTA - 1) {
            g_bar_count = 0;
            __threadfence();
            g_bar_phase = phase + 1;
        } else {
            while (g_bar_phase == phase) { }
        }
        __threadfence();
    }
    __syncthreads();
    phase++;
}

// ============================================================
// Persistent GRU recurrence. 128 CTAs x 192 threads.
// CTA c owns hidden dims k in [8c, 8c+8) for all 3 gates (24 cols of 3H).
// w_hh slice pinned in smem for the entire kernel.
// Thread map (GEMM): bg = tid&7 (float4 batch group), cl = tid>>3 (col 0..23).
// ============================================================
__global__ __launch_bounds__(NTHR, 1) void k_gru(const float* __restrict__ paddings,
                                                 const float* __restrict__ b_hh,
                                                 float* __restrict__ out,
                                                 int copies) {
    extern __shared__ float smem[];
    float* h_s = smem;                          // [1024][32]
    float4* w4_s = (float4*)(smem + W4_OFF);    // [256 kq][24 cl]
    float* gh_s = smem + GH_OFF;                // [24][32]
    float4* hs4 = (float4*)h_s;

    const int tid = threadIdx.x;
    const int c = blockIdx.x;
    const int bg = tid & 7;      // batch group (4 batches)
    const int cl = tid >> 3;     // column 0..23 (gate*8 + kl)

    // ---- load this CTA's 24 w columns into smem, k-major float4 blocks ----
    for (int idx = tid; idx < 256 * 24; idx += NTHR) {
        const int kq = idx / 24;
        const int wcl = idx - kq * 24;
        const int col = (wcl >> 3) * HH + c * 8 + (wcl & 7);
        w4_s[kq * 24 + wcl] = ((const float4*)(g_wT + (size_t)col * HH))[kq];
    }

    // gate-phase item indices (256 (kl,b) pairs over 192 threads)
    const int i0 = tid;
    const int i1 = tid + NTHR;
    const int kl0 = i0 & 7, b0 = i0 >> 3, k0 = c * 8 + kl0;
    const int kl1 = i1 & 7, b1 = i1 >> 3, k1 = c * 8 + kl1;
    const bool has1 = (i1 < 256);

    const float bh_r0 = b_hh[k0], bh_z0 = b_hh[HH + k0], bh_n0 = b_hh[2 * HH + k0];
    float bh_r1 = 0.f, bh_z1 = 0.f, bh_n1 = 0.f;
    if (has1) { bh_r1 = b_hh[k1]; bh_z1 = b_hh[HH + k1]; bh_n1 = b_hh[2 * HH + k1]; }

    unsigned phase = g_bar_phase;

    // zero h buffer 0 (rows owned by this CTA)
    for (int idx = tid; idx < 8 * BB; idx += NTHR)
        __stcg(&g_h[0][c * 8 * BB + idx], 0.f);
    __threadfence();
    grid_bar(phase);

    for (int t = 0; t < TT; t++) {
        // ---- prefetch gi / paddings for the gate phase ----
        const float* gib = g_gi + (size_t)t * BB * G3;
        const float gi_r0 = __ldg(gib + (size_t)b0 * G3 + k0);
        const float gi_z0 = __ldg(gib + (size_t)b0 * G3 + HH + k0);
        const float gi_n0 = __ldg(gib + (size_t)b0 * G3 + 2 * HH + k0);
        const float p0 = __ldg(paddings + t * BB + b0);
        float gi_r1 = 0.f, gi_z1 = 0.f, gi_n1 = 0.f, p1 = 0.f;
        if (has1) {
            gi_r1 = __ldg(gib + (size_t)b1 * G3 + k1);
            gi_z1 = __ldg(gib + (size_t)b1 * G3 + HH + k1);
            gi_n1 = __ldg(gib + (size_t)b1 * G3 + 2 * HH + k1);
            p1 = __ldg(paddings + t * BB + b1);
        }

        // ---- load h (prev step) into shared: [k][b] ----
        const float4* hb = (const float4*)g_h[t & 1];
        for (int idx = tid; idx < (HH * BB) / 4; idx += NTHR)
            hs4[idx] = __ldcg(hb + idx);
        __syncthreads();

        // ---- gh = h @ w_hh  (24 cols x 32 batches, w from smem) ----
        float acc0 = 0.f, acc1 = 0.f, acc2 = 0.f, acc3 = 0.f;
#pragma unroll 8
        for (int kq = 0; kq < HH / 4; kq++) {
            const float4 wv = w4_s[kq * 24 + cl];
            const float4 h0 = hs4[(kq * 4 + 0) * 8 + bg];
            const float4 h1 = hs4[(kq * 4 + 1) * 8 + bg];
            const float4 h2 = hs4[(kq * 4 + 2) * 8 + bg];
            const float4 h3 = hs4[(kq * 4 + 3) * 8 + bg];
            acc0 = fmaf(wv.x, h0.x, acc0); acc1 = fmaf(wv.x, h0.y, acc1);
            acc2 = fmaf(wv.x, h0.z, acc2); acc3 = fmaf(wv.x, h0.w, acc3);
            acc0 = fmaf(wv.y, h1.x, acc0); acc1 = fmaf(wv.y, h1.y, acc1);
            acc2 = fmaf(wv.y, h1.z, acc2); acc3 = fmaf(wv.y, h1.w, acc3);
            acc0 = fmaf(wv.z, h2.x, acc0); acc1 = fmaf(wv.z, h2.y, acc1);
            acc2 = fmaf(wv.z, h2.z, acc2); acc3 = fmaf(wv.z, h2.w, acc3);
            acc0 = fmaf(wv.w, h3.x, acc0); acc1 = fmaf(wv.w, h3.y, acc1);
            acc2 = fmaf(wv.w, h3.z, acc2); acc3 = fmaf(wv.w, h3.w, acc3);
        }
        gh_s[cl * 32 + bg * 4 + 0] = acc0;
        gh_s[cl * 32 + bg * 4 + 1] = acc1;
        gh_s[cl * 32 + bg * 4 + 2] = acc2;
        gh_s[cl * 32 + bg * 4 + 3] = acc3;
        __syncthreads();

        // ---- gates + state update + output ----
        {
            const float hr = gh_s[kl0 * 32 + b0] + bh_r0;
            const float hz = gh_s[(8 + kl0) * 32 + b0] + bh_z0;
            const float hn = gh_s[(16 + kl0) * 32 + b0] + bh_n0;
            const float r = 1.f / (1.f + expf(-(gi_r0 + hr)));
            const float z = 1.f / (1.f + expf(-(gi_z0 + hz)));
            const float n = tanhf(gi_n0 + r * hn);
            const float hold = h_s[k0 * 32 + b0];
            float hnew = (1.f - z) * n + z * hold;
            hnew = p0 * hold + (1.f - p0) * hnew;
            __stcg(&g_h[(t + 1) & 1][k0 * 32 + b0], hnew);
            const size_t ob = (size_t)(t * BB + b0) * HH + k0;
            for (int cp = 0; cp < copies; cp++) out[ob + (size_t)cp * OUT_COPY] = hnew;
        }
        if (has1) {
            const float hr = gh_s[kl1 * 32 + b1] + bh_r1;
            const float hz = gh_s[(8 + kl1) * 32 + b1] + bh_z1;
            const float hn = gh_s[(16 + kl1) * 32 + b1] + bh_n1;
            const float r = 1.f / (1.f + expf(-(gi_r1 + hr)));
            const float z = 1.f / (1.f + expf(-(gi_z1 + hz)));
            const float n = tanhf(gi_n1 + r * hn);
            const float hold = h_s[k1 * 32 + b1];
            float hnew = (1.f - z) * n + z * hold;
            hnew = p1 * hold + (1.f - p1) * hnew;
            __stcg(&g_h[(t + 1) & 1][k1 * 32 + b1], hnew);
            const size_t ob = (size_t)(t * BB + b1) * HH + k1;
            for (int cp = 0; cp < copies; cp++) out[ob + (size_t)cp * OUT_COPY] = hnew;
        }

        __threadfence();
        grid_bar(phase);
    }
}

// ============================================================
extern "C" void kernel_launch(void* const* d_in, const int* in_sizes, int n_in,
                              void* d_out, int out_size) {
    const float* input    = (const float*)d_in[0];
    const float* paddings = (const float*)d_in[1];
    const float* w_ih     = (const float*)d_in[2];
    const float* w_hh     = (const float*)d_in[3];
    const float* b_ih     = (const float*)d_in[4];
    const float* b_hh     = (const float*)d_in[5];
    float* out = (float*)d_out;

    int copies = out_size / OUT_COPY;
    if (copies < 1) copies = 1;
    if (copies > 2) copies = 2;

    const int smem_bytes = SMEM_FLOATS * (int)sizeof(float);  // 232448
    cudaFuncSetAttribute(k_gru, cudaFuncAttributeMaxDynamicSharedMemorySize, smem_bytes);

    k_transpose<<<dim3(G3 / 32, HH / 32), dim3(32, 8)>>>(w_hh);
    k_gemm_gi<<<dim3(G3 / 128, (TT * BB) / 128), 256>>>(input, w_ih, b_ih);
    k_gru<<<NCTA, NTHR, smem_bytes>>>(paddings, b_hh, out, copies);
}

// round 4
// speedup vs baseline: 1.8902x; 1.0358x over previous
#include <cuda_runtime.h>
#include <math.h>

#define TT 512
#define BB 32
#define II 512
#define HH 1024
#define G3 3072
#define NCTA 128
#define NTHR 384
#define OUT_COPY (TT * BB * HH)

// smem partition for k_gru (floats):
//   h_s  : [0, 32768)        h state [k][b]             131072 B
//   w4_s : [32768, 57344)    w as float4 [kq][24 cols]   98304 B
//   gh_s : [57344, 58112)    gh reduce/exchange [24][32]  3072 B
// total 58112 floats = 232448 B = exactly the 227 KB opt-in max.
#define SMEM_FLOATS 58112
#define W4_OFF 32768
#define GH_OFF 57344

typedef unsigned long long ull;
union f2u { ull u; float2 f; };

__device__ __forceinline__ ull fdup(float x) {
    ull r;
    asm("mov.b64 %0, {%1, %1};" : "=l"(r) : "r"(__float_as_uint(x)));
    return r;
}
__device__ __forceinline__ void fma2(ull& d, ull a, ull b) {
    asm("fma.rn.f32x2 %0, %1, %2, %3;" : "=l"(d) : "l"(a), "l"(b), "l"(d));
}

// -------- static device scratch --------
__device__ float g_gi[(size_t)TT * BB * G3];   // gi = X@w_ih + b_ih
__device__ float g_wT[G3 * HH];                // w_hh transposed: [3H][H]
__device__ float g_h[2][HH * BB];              // ping-pong hidden state [k][b]
__device__ unsigned g_bar_count = 0;
__device__ volatile unsigned g_bar_phase = 0;

// ============================================================
// Transpose w_hh [H][3H] -> g_wT [3H][H]
// ============================================================
__global__ void k_transpose(const float* __restrict__ whh) {
    __shared__ float tile[32][33];
    const int col0 = blockIdx.x * 32;
    const int row0 = blockIdx.y * 32;
    const int tx = threadIdx.x, ty = threadIdx.y;
#pragma unroll
    for (int r = ty; r < 32; r += 8)
        tile[r][tx] = whh[(row0 + r) * G3 + col0 + tx];
    __syncthreads();
#pragma unroll
    for (int r = ty; r < 32; r += 8)
        g_wT[(size_t)(col0 + r) * HH + row0 + tx] = tile[tx][r];
}

// ============================================================
// Input GEMM: gi = X@W + bias. M=16384, K=512, N=3072.
// BM=BN=128, BK=8, TM=TN=8 (cols packed f32x2), 256 thr
// ============================================================
__global__ __launch_bounds__(256) void k_gemm_gi(const float* __restrict__ X,
                                                 const float* __restrict__ W,
                                                 const float* __restrict__ bias) {
    __shared__ float a_s[8][128];
    __shared__ float b_s[8][128];
    const int bm = blockIdx.y * 128;
    const int bn = blockIdx.x * 128;
    const int tid = threadIdx.x;
    const int tx = tid & 15;
    const int ty = tid >> 4;

    const int arow = tid >> 1;
    const int ak   = (tid & 1) * 4;
    const int bk   = tid >> 5;
    const int bnc  = (tid & 31) * 4;

    ull acc[8][4];  // 8 rows x 4 packed col-pairs
#pragma unroll
    for (int i = 0; i < 8; i++)
#pragma unroll
        for (int j = 0; j < 4; j++) acc[i][j] = 0ull;

    const float* Xp = X + (size_t)(bm + arow) * II + ak;
    const float* Wp = W + (size_t)bk * G3 + bn + bnc;

    for (int k0 = 0; k0 < II; k0 += 8) {
        float4 av = *(const float4*)(Xp + k0);
        float4 bv = *(const float4*)(Wp + (size_t)k0 * G3);
        a_s[ak + 0][arow] = av.x;
        a_s[ak + 1][arow] = av.y;
        a_s[ak + 2][arow] = av.z;
        a_s[ak + 3][arow] = av.w;
        *(float4*)&b_s[bk][bnc] = bv;
        __syncthreads();
#pragma unroll
        for (int kk = 0; kk < 8; kk++) {
            float4 a0 = *(const float4*)&a_s[kk][ty * 8];
            float4 a1 = *(const float4*)&a_s[kk][ty * 8 + 4];
            ulonglong2 bp0 = *(const ulonglong2*)&b_s[kk][tx * 8];
            ulonglong2 bp1 = *(const ulonglong2*)&b_s[kk][tx * 8 + 4];
            float ar[8] = {a0.x, a0.y, a0.z, a0.w, a1.x, a1.y, a1.z, a1.w};
#pragma unroll
            for (int i = 0; i < 8; i++) {
                const ull ad = fdup(ar[i]);
                fma2(acc[i][0], ad, bp0.x);
                fma2(acc[i][1], ad, bp0.y);
                fma2(acc[i][2], ad, bp1.x);
                fma2(acc[i][3], ad, bp1.y);
            }
        }
        __syncthreads();
    }
    float4 bv0 = *(const float4*)(bias + bn + tx * 8);
    float4 bv1 = *(const float4*)(bias + bn + tx * 8 + 4);
#pragma unroll
    for (int i = 0; i < 8; i++) {
        const size_t row = (size_t)(bm + ty * 8 + i);
        f2u u0, u1, u2, u3;
        u0.u = acc[i][0]; u1.u = acc[i][1]; u2.u = acc[i][2]; u3.u = acc[i][3];
        float4 o0, o1;
        o0.x = u0.f.x + bv0.x; o0.y = u0.f.y + bv0.y;
        o0.z = u1.f.x + bv0.z; o0.w = u1.f.y + bv0.w;
        o1.x = u2.f.x + bv1.x; o1.y = u2.f.y + bv1.y;
        o1.z = u3.f.x + bv1.z; o1.w = u3.f.y + bv1.w;
        *(float4*)&g_gi[row * G3 + bn + tx * 8]     = o0;
        *(float4*)&g_gi[row * G3 + bn + tx * 8 + 4] = o1;
    }
}

// ============================================================
// Grid-wide barrier (all NCTA CTAs wave-1 resident: 1 CTA/SM by smem)
// ============================================================
__device__ __forceinline__ void grid_bar(unsigned& phase) {
    __syncthreads();
    if (threadIdx.x == 0) {
        unsigned old = atomicAdd(&g_bar_count, 1u);
        if (old == NCTA - 1) {
            g_bar_count = 0;
            __threadfence();
            g_bar_phase = phase + 1;
        } else {
            while (g_bar_phase == phase) { }
        }
        __threadfence();
    }
    __syncthreads();
    phase++;
}

// ============================================================
// Persistent GRU recurrence. 128 CTAs x 384 threads.
// CTA c owns hidden dims k in [8c, 8c+8) (24 cols of 3H).
// K split in two halves (tid<192 -> K[0:512), tid>=192 -> K[512:1024)).
// Per thread: col cl=r>>3 (0..23), batch group bg=r&7 (4 batches as 2 f32x2).
// ============================================================
__global__ __launch_bounds__(NTHR, 1) void k_gru(const float* __restrict__ paddings,
                                                 const float* __restrict__ b_hh,
                                                 float* __restrict__ out,
                                                 int copies) {
    extern __shared__ float smem[];
    float* h_s = smem;                               // [1024][32]
    float4* w4_s = (float4*)(smem + W4_OFF);         // [256 kq][24 cl]
    float* gh_s = smem + GH_OFF;                     // [24][32]
    const ulonglong2* hsd = (const ulonglong2*)h_s;  // [k][bg] packed pairs
    float4* hs4 = (float4*)h_s;

    const int tid = threadIdx.x;
    const int c = blockIdx.x;
    const int kh = (tid >= 192) ? 1 : 0;
    const int r = tid - kh * 192;
    const int bg = r & 7;
    const int cl = r >> 3;
    const int kq0 = kh * 128;

    // ---- load this CTA's 24 w columns into smem ----
    for (int idx = tid; idx < 256 * 24; idx += NTHR) {
        const int kq = idx / 24;
        const int wcl = idx - kq * 24;
        const int col = (wcl >> 3) * HH + c * 8 + (wcl & 7);
        w4_s[kq * 24 + wcl] = ((const float4*)(g_wT + (size_t)col * HH))[kq];
    }

    // gate-phase mapping: tid<256 handles one (kl,b)
    const int kl0 = tid & 7, b0 = tid >> 3, k0 = c * 8 + kl0;
    const bool gate_th = (tid < 256);
    float bh_r0 = 0.f, bh_z0 = 0.f, bh_n0 = 0.f;
    if (gate_th) {
        bh_r0 = b_hh[k0]; bh_z0 = b_hh[HH + k0]; bh_n0 = b_hh[2 * HH + k0];
    }

    unsigned phase = g_bar_phase;

    // zero h buffer 0 (rows owned by this CTA)
    for (int idx = tid; idx < 8 * BB; idx += NTHR)
        __stcg(&g_h[0][c * 8 * BB + idx], 0.f);
    __threadfence();
    grid_bar(phase);

    for (int t = 0; t < TT; t++) {
        // ---- prefetch gi / paddings for the gate phase ----
        float gi_r0 = 0.f, gi_z0 = 0.f, gi_n0 = 0.f, p0 = 0.f;
        if (gate_th) {
            const float* gib = g_gi + (size_t)t * BB * G3;
            gi_r0 = __ldg(gib + (size_t)b0 * G3 + k0);
            gi_z0 = __ldg(gib + (size_t)b0 * G3 + HH + k0);
            gi_n0 = __ldg(gib + (size_t)b0 * G3 + 2 * HH + k0);
            p0 = __ldg(paddings + t * BB + b0);
        }

        // ---- load h (prev step) into shared: [k][b] ----
        const float4* hb = (const float4*)g_h[t & 1];
        for (int idx = tid; idx < (HH * BB) / 4; idx += NTHR)
            hs4[idx] = __ldcg(hb + idx);
        __syncthreads();

        // ---- gh = h @ w_hh  (K-half per thread, packed f32x2) ----
        ull acc0 = 0ull, acc1 = 0ull;   // {b0,b1}, {b2,b3}
#pragma unroll 4
        for (int kq = kq0; kq < kq0 + 128; kq++) {
            const float4 wv = w4_s[kq * 24 + cl];
            const ulonglong2 h0 = hsd[(kq * 4 + 0) * 8 + bg];
            const ulonglong2 h1 = hsd[(kq * 4 + 1) * 8 + bg];
            const ulonglong2 h2 = hsd[(kq * 4 + 2) * 8 + bg];
            const ulonglong2 h3 = hsd[(kq * 4 + 3) * 8 + bg];
            const ull w0 = fdup(wv.x), w1 = fdup(wv.y), w2 = fdup(wv.z), w3 = fdup(wv.w);
            fma2(acc0, w0, h0.x); fma2(acc1, w0, h0.y);
            fma2(acc0, w1, h1.x); fma2(acc1, w1, h1.y);
            fma2(acc0, w2, h2.x); fma2(acc1, w2, h2.y);
            fma2(acc0, w3, h3.x); fma2(acc1, w3, h3.y);
        }

        // ---- reduce the two K-halves in gh_s ----
        f2u u0, u1; u0.u = acc0; u1.u = acc1;
        if (kh) {
            float4 o; o.x = u0.f.x; o.y = u0.f.y; o.z = u1.f.x; o.w = u1.f.y;
            *(float4*)&gh_s[cl * 32 + bg * 4] = o;
        }
        __syncthreads();
        if (!kh) {
            float4 o = *(const float4*)&gh_s[cl * 32 + bg * 4];
            o.x += u0.f.x; o.y += u0.f.y; o.z += u1.f.x; o.w += u1.f.y;
            *(float4*)&gh_s[cl * 32 + bg * 4] = o;
        }
        __syncthreads();

        // ---- gates + state update + output ----
        if (gate_th) {
            const float hr = gh_s[kl0 * 32 + b0] + bh_r0;
            const float hz = gh_s[(8 + kl0) * 32 + b0] + bh_z0;
            const float hn = gh_s[(16 + kl0) * 32 + b0] + bh_n0;
            const float rg = 1.f / (1.f + expf(-(gi_r0 + hr)));
            const float zg = 1.f / (1.f + expf(-(gi_z0 + hz)));
            const float ng = tanhf(gi_n0 + rg * hn);
            const float hold = h_s[k0 * 32 + b0];
            float hnew = (1.f - zg) * ng + zg * hold;
            hnew = p0 * hold + (1.f - p0) * hnew;
            __stcg(&g_h[(t + 1) & 1][k0 * 32 + b0], hnew);
            const size_t ob = (size_t)(t * BB + b0) * HH + k0;
            for (int cp = 0; cp < copies; cp++) out[ob + (size_t)cp * OUT_COPY] = hnew;
            __threadfence();
        }
        grid_bar(phase);
    }
}

// ============================================================
extern "C" void kernel_launch(void* const* d_in, const int* in_sizes, int n_in,
                              void* d_out, int out_size) {
    const float* input    = (const float*)d_in[0];
    const float* paddings = (const float*)d_in[1];
    const float* w_ih     = (const float*)d_in[2];
    const float* w_hh     = (const float*)d_in[3];
    const float* b_ih     = (const float*)d_in[4];
    const float* b_hh     = (const float*)d_in[5];
    float* out = (float*)d_out;

    int copies = out_size / OUT_COPY;
    if (copies < 1) copies = 1;
    if (copies > 2) copies = 2;

    const int smem_bytes = SMEM_FLOATS * (int)sizeof(float);  // 232448
    cudaFuncSetAttribute(k_gru, cudaFuncAttributeMaxDynamicSharedMemorySize, smem_bytes);

    k_transpose<<<dim3(G3 / 32, HH / 32), dim3(32, 8)>>>(w_hh);
    k_gemm_gi<<<dim3(G3 / 128, (TT * BB) / 128), 256>>>(input, w_ih, b_ih);
    k_gru<<<NCTA, NTHR, smem_bytes>>>(paddings, b_hh, out, copies);
}

// round 5
// speedup vs baseline: 3.0264x; 1.6011x over previous
#include <cuda_runtime.h>
#include <math.h>

#define TT 512
#define BB 32
#define II 512
#define HH 1024
#define G3 3072
#define NCTA 128
#define NTHR 384
#define OUT_COPY (TT * BB * HH)

typedef unsigned long long ull;
union f2u { ull u; float2 f; };

static __device__ __forceinline__ ull fdup(float x) {
    ull r;
    asm("mov.b64 %0, {%1, %1};" : "=l"(r) : "r"(__float_as_uint(x)));
    return r;
}
static __device__ __forceinline__ void fma2(ull& d, ull a, ull b) {
    asm("fma.rn.f32x2 %0, %1, %2, %3;" : "=l"(d) : "l"(a), "l"(b), "l"(d));
}
static __device__ __forceinline__ ull add2(ull a, ull b) {
    ull d;
    asm("add.rn.f32x2 %0, %1, %2;" : "=l"(d) : "l"(a), "l"(b));
    return d;
}

// -------- static device scratch --------
__device__ float g_gi[(size_t)TT * BB * G3];     // gi = X@w_ih + b_ih
__device__ float g_wT[G3 * HH];                  // w_hh transposed: [3H][H]
__device__ float4 g_h[2][HH * BB / 4];           // ping-pong hidden state [k][b]
__device__ unsigned g_bar_count = 0;
__device__ volatile unsigned g_bar_phase = 0;

// ============================================================
// Transpose w_hh [H][3H] -> g_wT [3H][H]
// ============================================================
__global__ void k_transpose(const float* __restrict__ whh) {
    __shared__ float tile[32][33];
    const int col0 = blockIdx.x * 32;
    const int row0 = blockIdx.y * 32;
    const int tx = threadIdx.x, ty = threadIdx.y;
#pragma unroll
    for (int r = ty; r < 32; r += 8)
        tile[r][tx] = whh[(row0 + r) * G3 + col0 + tx];
    __syncthreads();
#pragma unroll
    for (int r = ty; r < 32; r += 8)
        g_wT[(size_t)(col0 + r) * HH + row0 + tx] = tile[tx][r];
}

// ============================================================
// Input GEMM: gi = X@W + bias. M=16384, K=512, N=3072.
// BM=BN=128, BK=8, TM=TN=8 (cols packed f32x2), 256 thr
// ============================================================
__global__ __launch_bounds__(256) void k_gemm_gi(const float* __restrict__ X,
                                                 const float* __restrict__ W,
                                                 const float* __restrict__ bias) {
    __shared__ float a_s[8][128];
    __shared__ float b_s[8][128];
    const int bm = blockIdx.y * 128;
    const int bn = blockIdx.x * 128;
    const int tid = threadIdx.x;
    const int tx = tid & 15;
    const int ty = tid >> 4;

    const int arow = tid >> 1;
    const int ak   = (tid & 1) * 4;
    const int bk   = tid >> 5;
    const int bnc  = (tid & 31) * 4;

    ull acc[8][4];
#pragma unroll
    for (int i = 0; i < 8; i++)
#pragma unroll
        for (int j = 0; j < 4; j++) acc[i][j] = 0ull;

    const float* Xp = X + (size_t)(bm + arow) * II + ak;
    const float* Wp = W + (size_t)bk * G3 + bn + bnc;

    for (int k0 = 0; k0 < II; k0 += 8) {
        float4 av = *(const float4*)(Xp + k0);
        float4 bv = *(const float4*)(Wp + (size_t)k0 * G3);
        a_s[ak + 0][arow] = av.x;
        a_s[ak + 1][arow] = av.y;
        a_s[ak + 2][arow] = av.z;
        a_s[ak + 3][arow] = av.w;
        *(float4*)&b_s[bk][bnc] = bv;
        __syncthreads();
#pragma unroll
        for (int kk = 0; kk < 8; kk++) {
            float4 a0 = *(const float4*)&a_s[kk][ty * 8];
            float4 a1 = *(const float4*)&a_s[kk][ty * 8 + 4];
            ulonglong2 bp0 = *(const ulonglong2*)&b_s[kk][tx * 8];
            ulonglong2 bp1 = *(const ulonglong2*)&b_s[kk][tx * 8 + 4];
            float ar[8] = {a0.x, a0.y, a0.z, a0.w, a1.x, a1.y, a1.z, a1.w};
#pragma unroll
            for (int i = 0; i < 8; i++) {
                const ull ad = fdup(ar[i]);
                fma2(acc[i][0], ad, bp0.x);
                fma2(acc[i][1], ad, bp0.y);
                fma2(acc[i][2], ad, bp1.x);
                fma2(acc[i][3], ad, bp1.y);
            }
        }
        __syncthreads();
    }
    float4 bv0 = *(const float4*)(bias + bn + tx * 8);
    float4 bv1 = *(const float4*)(bias + bn + tx * 8 + 4);
#pragma unroll
    for (int i = 0; i < 8; i++) {
        const size_t row = (size_t)(bm + ty * 8 + i);
        f2u u0, u1, u2, u3;
        u0.u = acc[i][0]; u1.u = acc[i][1]; u2.u = acc[i][2]; u3.u = acc[i][3];
        float4 o0, o1;
        o0.x = u0.f.x + bv0.x; o0.y = u0.f.y + bv0.y;
        o0.z = u1.f.x + bv0.z; o0.w = u1.f.y + bv0.w;
        o1.x = u2.f.x + bv1.x; o1.y = u2.f.y + bv1.y;
        o1.z = u3.f.x + bv1.z; o1.w = u3.f.y + bv1.w;
        *(float4*)&g_gi[row * G3 + bn + tx * 8]     = o0;
        *(float4*)&g_gi[row * G3 + bn + tx * 8 + 4] = o1;
    }
}

// ============================================================
// Grid-wide barrier
// ============================================================
__device__ __forceinline__ void grid_bar(unsigned& phase) {
    __syncthreads();
    if (threadIdx.x == 0) {
        unsigned old = atomicAdd(&g_bar_count, 1u);
        if (old == NCTA - 1) {
            g_bar_count = 0;
            __threadfence();
            g_bar_phase = phase + 1;
        } else {
            while (g_bar_phase == phase) { }
        }
        __threadfence();
    }
    __syncthreads();
    phase++;
}

// ============================================================
// Persistent GRU recurrence. 128 CTAs x 384 threads (12 warps).
// CTA c owns 24 cols of 3H: col = g*HH + c*8 + kl.
// Thread: warp w -> cg=w>>2 (8 cols), ksg=w&3; lane -> ks_in=l>>2, bgrp=l&3.
// Each thread: 8 cols x 8 batches x 32 k. Register-blocked: acc = 32 f32x2.
// h & w in smem with XOR swizzle (keyed on kseg&7) for conflict-free LDS.128.
// In-warp butterfly reduce over ks_in; cross-warp ksg partials aliased on h rows.
// smem: h 131072 B [words 0,32768) + w 98304 B [32768, 57344) = 229376 B.
// ============================================================
__global__ __launch_bounds__(NTHR, 1) void k_gru(const float* __restrict__ paddings,
                                                 const float* __restrict__ b_hh,
                                                 float* __restrict__ out,
                                                 int copies) {
    extern __shared__ float smem[];
    const ulonglong2* hsu = (const ulonglong2*)smem;   // h as 16-B units [k*8 + swz(u)]
    float4* hs4 = (float4*)smem;
    float4* w4s = (float4*)(smem + 32768);             // [kq*24 + cg*8 + (j^swz)]

    const int tid = threadIdx.x;
    const int c = blockIdx.x;
    const int wid = tid >> 5, lane = tid & 31;
    const int cg = wid >> 2, ksg = wid & 3;
    const int ks_in = lane >> 2, bgrp = lane & 3;
    const int kseg = ksg * 8 + ks_in;     // 0..31, thread's k-range = [kseg*32, +32)
    const int swz = ks_in;                // == kseg & 7
    const int kbase = kseg * 32;

    // ---- load this CTA's 24 w columns into smem (swizzled) ----
    for (int idx = tid; idx < 6144; idx += NTHR) {
        const int kq = idx / 24;
        const int cl = idx - kq * 24;
        const int col = (cl >> 3) * HH + c * 8 + (cl & 7);
        const int du = kq * 24 + (cl & ~7) + ((cl & 7) ^ ((kq >> 3) & 7));
        w4s[du] = ((const float4*)(g_wT + (size_t)col * HH))[kq];
    }

    // gate-phase mapping: tid<256 -> one (kl, b)
    const int kl0 = tid & 7, b0 = tid >> 3, k0 = c * 8 + kl0;
    const bool gate_th = (tid < 256);
    float bhr = 0.f, bhz = 0.f, bhn = 0.f;
    if (gate_th) { bhr = b_hh[k0]; bhz = b_hh[HH + k0]; bhn = b_hh[2 * HH + k0]; }

    // partial-sum alias region: rows [8c+8, 8c+116) of h_s (never this CTA's own rows)
    const int pbase = (8 * c + 8) * 32;   // word offset, wrapped with & 32767

    unsigned phase = g_bar_phase;

    // zero h buffer 0 (rows owned by this CTA)
    float* gh0 = (float*)g_h[0];
    for (int idx = tid; idx < 8 * BB; idx += NTHR)
        __stcg(&gh0[c * 8 * BB + idx], 0.f);
    __threadfence();
    grid_bar(phase);

    for (int t = 0; t < TT; t++) {
        // ---- prefetch gi / paddings ----
        float gir = 0.f, giz = 0.f, gin = 0.f, p0 = 0.f;
        if (gate_th) {
            const float* gib = g_gi + (size_t)t * BB * G3;
            gir = __ldg(gib + (size_t)b0 * G3 + k0);
            giz = __ldg(gib + (size_t)b0 * G3 + HH + k0);
            gin = __ldg(gib + (size_t)b0 * G3 + 2 * HH + k0);
            p0 = __ldg(paddings + t * BB + b0);
        }

        // ---- stage h into swizzled smem ----
        const float4* hg = g_h[t & 1];
#pragma unroll 4
        for (int g = tid; g < 8192; g += NTHR) {
            const int k = g >> 3, u = g & 7;
            hs4[k * 8 + (u ^ ((k >> 5) & 7))] = __ldcg(&hg[g]);
        }
        __syncthreads();

        // ---- gh = h @ w_hh : 8 cols x 8 batches x 32 k per thread ----
        ull acc[8][4];
#pragma unroll
        for (int j = 0; j < 8; j++)
#pragma unroll
            for (int p = 0; p < 4; p++) acc[j][p] = 0ull;

        const int wbase = kseg * 8 * 24 + cg * 8;
#pragma unroll
        for (int m = 0; m < 8; m++) {
            float4 wv[8];
#pragma unroll
            for (int j = 0; j < 8; j++)
                wv[j] = w4s[wbase + m * 24 + (j ^ swz)];
#pragma unroll
            for (int q = 0; q < 4; q++) {
                const int k = kbase + m * 4 + q;
                const ulonglong2 ha = hsu[k * 8 + ((2 * bgrp) ^ swz)];
                const ulonglong2 hc = hsu[k * 8 + ((2 * bgrp + 1) ^ swz)];
#pragma unroll
                for (int j = 0; j < 8; j++) {
                    const float ws = ((const float*)&wv[j])[q];
                    const ull wd = fdup(ws);
                    fma2(acc[j][0], wd, ha.x);
                    fma2(acc[j][1], wd, ha.y);
                    fma2(acc[j][2], wd, hc.x);
                    fma2(acc[j][3], wd, hc.y);
                }
            }
        }

        // ---- in-warp butterfly reduce over ks_in (lane bits 2..4) ----
#pragma unroll
        for (int ofs = 4; ofs <= 16; ofs <<= 1)
#pragma unroll
            for (int j = 0; j < 8; j++)
#pragma unroll
                for (int p = 0; p < 4; p++) {
                    const ull o = __shfl_xor_sync(0xffffffffu, acc[j][p], ofs);
                    acc[j][p] = add2(acc[j][p], o);
                }

        __syncthreads();   // all GEMM h reads done before aliasing partials on h rows

        // ---- write ksg partials (stride-36 rows: conflict-free gate reads) ----
        if (ks_in == 0) {
#pragma unroll
            for (int j = 0; j < 8; j++) {
                const int flat = (ksg * 24 + cg * 8 + j) * 36 + bgrp * 8;
                const int w1 = (pbase + flat) & 32767;
                const int w2 = (pbase + flat + 4) & 32767;
                *(ulonglong2*)&smem[w1] = make_ulonglong2(acc[j][0], acc[j][1]);
                *(ulonglong2*)&smem[w2] = make_ulonglong2(acc[j][2], acc[j][3]);
            }
        }
        __syncthreads();

        // ---- gates + state update + output ----
        if (gate_th) {
            float gh[3];
#pragma unroll
            for (int g = 0; g < 3; g++) {
                float s = 0.f;
#pragma unroll
                for (int ks = 0; ks < 4; ks++) {
                    const int flat = (ks * 24 + g * 8 + kl0) * 36 + b0;
                    s += smem[(pbase + flat) & 32767];
                }
                gh[g] = s;
            }
            // hold from swizzled h_s (own rows, untouched by partials)
            const int hw = k0 * 32 + (((b0 >> 2) ^ ((k0 >> 5) & 7)) << 2) + (b0 & 3);
            const float hold = smem[hw];
            const float r = 1.f / (1.f + expf(-(gir + gh[0] + bhr)));
            const float z = 1.f / (1.f + expf(-(giz + gh[1] + bhz)));
            const float n = tanhf(gin + r * (gh[2] + bhn));
            float hnew = (1.f - z) * n + z * hold;
            hnew = p0 * hold + (1.f - p0) * hnew;
            __stcg(&((float*)g_h[(t + 1) & 1])[k0 * 32 + b0], hnew);
            const size_t ob = (size_t)(t * BB + b0) * HH + k0;
            for (int cp = 0; cp < copies; cp++) out[ob + (size_t)cp * OUT_COPY] = hnew;
            __threadfence();
        }
        grid_bar(phase);
    }
}

// ============================================================
extern "C" void kernel_launch(void* const* d_in, const int* in_sizes, int n_in,
                              void* d_out, int out_size) {
    const float* input    = (const float*)d_in[0];
    const float* paddings = (const float*)d_in[1];
    const float* w_ih     = (const float*)d_in[2];
    const float* w_hh     = (const float*)d_in[3];
    const float* b_ih     = (const float*)d_in[4];
    const float* b_hh     = (const float*)d_in[5];
    float* out = (float*)d_out;

    int copies = out_size / OUT_COPY;
    if (copies < 1) copies = 1;
    if (copies > 2) copies = 2;

    const int smem_bytes = 57344 * (int)sizeof(float);  // 229376 B
    cudaFuncSetAttribute(k_gru, cudaFuncAttributeMaxDynamicSharedMemorySize, smem_bytes);

    k_transpose<<<dim3(G3 / 32, HH / 32), dim3(32, 8)>>>(w_hh);
    k_gemm_gi<<<dim3(G3 / 128, (TT * BB) / 128), 256>>>(input, w_ih, b_ih);
    k_gru<<<NCTA, NTHR, smem_bytes>>>(paddings, b_hh, out, copies);
}

// round 7
// speedup vs baseline: 3.4363x; 1.1354x over previous
#include <cuda_runtime.h>
#include <cuda_bf16.h>
#include <math.h>
#include <stdint.h>

#define TT 512
#define BB 32
#define II 512
#define HH 1024
#define G3 3072
#define NCTA 128
#define NTHR 256
#define OUT_COPY (TT * BB * HH)

#define KE 1536          // K_eff for input gemm (512*3)
#define WS_ROW 776       // 768 + 8 pad (bf16 elems)
#define WS_BYTES (96 * WS_ROW * 2)          // 148992
#define HS_OFF WS_BYTES
#define SMEM_GRU (WS_BYTES + 32 * WS_ROW * 2)  // 198656

typedef unsigned long long ull;

// -------- static device scratch --------
__device__ float g_gi[(size_t)TT * BB * G3];          // gi = X@w_ih + b_ih
__device__ float g_wT[G3 * HH];                       // w_hh^T fp32 [3H][H]
__device__ __nv_bfloat16 g_xs[(size_t)TT * BB * KE];  // X split [row][hi|hi|lo]
__device__ __nv_bfloat16 g_wst[(size_t)G3 * KE];      // w_ih^T split [n][hi|lo|hi]
__device__ float g_h[2][BB * HH];                     // fp32 hidden [b][k]
__device__ __nv_bfloat16 g_hbf[2][2][BB * HH];        // bf16 hi/lo of h [b][k]
__device__ float g_part[NCTA * BB * 96];              // split-K partials [blk][b][m]
__device__ unsigned g_bar_count = 0;
__device__ volatile unsigned g_bar_phase = 0;

// bf16 mma m16n8k16: D(f32) += A(bf16,row) * B(bf16,col)
static __device__ __forceinline__ void mma_bf16(float* d, const uint32_t* a,
                                                const uint32_t* b) {
    asm volatile(
        "mma.sync.aligned.m16n8k16.row.col.f32.bf16.bf16.f32 "
        "{%0,%1,%2,%3}, {%4,%5,%6,%7}, {%8,%9}, {%0,%1,%2,%3};"
        : "+f"(d[0]), "+f"(d[1]), "+f"(d[2]), "+f"(d[3])
        : "r"(a[0]), "r"(a[1]), "r"(a[2]), "r"(a[3]), "r"(b[0]), "r"(b[1]));
}

static __device__ __forceinline__ void split_bf16(float x, __nv_bfloat16& hi,
                                                  __nv_bfloat16& lo) {
    hi = __float2bfloat16(x);
    lo = __float2bfloat16(x - __bfloat162float(hi));
}

// ============================================================
// Transpose w_hh [H][3H] -> g_wT [3H][H] (fp32)
// ============================================================
__global__ void k_transpose(const float* __restrict__ whh) {
    __shared__ float tile[32][33];
    const int col0 = blockIdx.x * 32;
    const int row0 = blockIdx.y * 32;
    const int tx = threadIdx.x, ty = threadIdx.y;
#pragma unroll
    for (int r = ty; r < 32; r += 8)
        tile[r][tx] = whh[(row0 + r) * G3 + col0 + tx];
    __syncthreads();
#pragma unroll
    for (int r = ty; r < 32; r += 8)
        g_wT[(size_t)(col0 + r) * HH + row0 + tx] = tile[tx][r];
}

// ============================================================
// Split X -> g_xs [hi | hi | lo] along K
// ============================================================
__global__ void k_split_x(const float* __restrict__ X) {
    const size_t idx = (size_t)blockIdx.x * 256 + threadIdx.x;
    const float x = X[idx];
    const size_t r = idx >> 9;          // / 512
    const int k = (int)(idx & 511);
    __nv_bfloat16 hi, lo; split_bf16(x, hi, lo);
    __nv_bfloat16* row = g_xs + r * KE;
    row[k] = hi; row[512 + k] = hi; row[1024 + k] = lo;
}

// ============================================================
// Split+transpose w_ih [512][3072] -> g_wst [3072][hi | lo | hi]
// ============================================================
__global__ void k_split_wt(const float* __restrict__ wih) {
    __shared__ float tile[32][33];
    const int col0 = blockIdx.x * 32;   // 3072 dim
    const int row0 = blockIdx.y * 32;   // 512 dim
    const int tx = threadIdx.x, ty = threadIdx.y;
#pragma unroll
    for (int r = ty; r < 32; r += 8)
        tile[r][tx] = wih[(row0 + r) * G3 + col0 + tx];
    __syncthreads();
#pragma unroll
    for (int r = ty; r < 32; r += 8) {
        const float x = tile[tx][r];
        __nv_bfloat16 hi, lo; split_bf16(x, hi, lo);
        __nv_bfloat16* row = g_wst + (size_t)(col0 + r) * KE + row0 + tx;
        row[0] = hi; row[512] = lo; row[1024] = hi;
    }
}

// ============================================================
// Input GEMM (HMMA bf16x3): gi = X@W + bias.
// M=16384, N=3072, K_eff=1536. BM=BN=128, BK=32, 256 thr (8 warps 4m x 2n).
// ============================================================
__global__ __launch_bounds__(256) void k_gemm_gi(const float* __restrict__ bias) {
    __shared__ __nv_bfloat16 a_s[2][128 * 40];
    __shared__ __nv_bfloat16 b_s[2][128 * 40];

    const int bm = blockIdx.y * 128;
    const int bn = blockIdx.x * 128;
    const int tid = threadIdx.x;
    const int wid = tid >> 5, lane = tid & 31;
    const int g = lane >> 2, tg = lane & 3;
    const int mw = wid & 3, nw = wid >> 2;   // warp tile [mw*32,+32) x [nw*64,+64)

    const int grow = tid >> 1;               // 0..127
    const int gco4 = (tid & 1) * 2;          // uint4 offset within 32-elem chunk

    const uint4* ap = (const uint4*)(g_xs + (size_t)(bm + grow) * KE);
    const uint4* bp = (const uint4*)(g_wst + (size_t)(bn + grow) * KE);

    float acc[2][8][4];
#pragma unroll
    for (int i = 0; i < 2; i++)
#pragma unroll
        for (int j = 0; j < 8; j++)
#pragma unroll
            for (int p = 0; p < 4; p++) acc[i][j][p] = 0.f;

    // prologue: chunk 0
    {
        uint4 av0 = ap[gco4], av1 = ap[gco4 + 1];
        uint4 bv0 = bp[gco4], bv1 = bp[gco4 + 1];
        *(uint4*)&a_s[0][grow * 40 + gco4 * 8] = av0;
        *(uint4*)&a_s[0][grow * 40 + gco4 * 8 + 8] = av1;
        *(uint4*)&b_s[0][grow * 40 + gco4 * 8] = bv0;
        *(uint4*)&b_s[0][grow * 40 + gco4 * 8 + 8] = bv1;
    }
    __syncthreads();

    int buf = 0;
    for (int kc = 0; kc < KE / 32; kc++) {
        uint4 av0, av1, bv0, bv1;
        if (kc < KE / 32 - 1) {
            av0 = ap[(kc + 1) * 4 + gco4]; av1 = ap[(kc + 1) * 4 + gco4 + 1];
            bv0 = bp[(kc + 1) * 4 + gco4]; bv1 = bp[(kc + 1) * 4 + gco4 + 1];
        }
#pragma unroll
        for (int kk = 0; kk < 2; kk++) {
            const int ka = kk * 16 + 2 * tg;
            uint32_t afr[2][4];
#pragma unroll
            for (int mt = 0; mt < 2; mt++) {
                const int ar = mw * 32 + mt * 16 + g;
                afr[mt][0] = *(const uint32_t*)&a_s[buf][ar * 40 + ka];
                afr[mt][1] = *(const uint32_t*)&a_s[buf][(ar + 8) * 40 + ka];
                afr[mt][2] = *(const uint32_t*)&a_s[buf][ar * 40 + ka + 8];
                afr[mt][3] = *(const uint32_t*)&a_s[buf][(ar + 8) * 40 + ka + 8];
            }
#pragma unroll
            for (int nt = 0; nt < 8; nt++) {
                const int br = nw * 64 + nt * 8 + g;
                uint32_t bfr[2];
                bfr[0] = *(const uint32_t*)&b_s[buf][br * 40 + ka];
                bfr[1] = *(const uint32_t*)&b_s[buf][br * 40 + ka + 8];
                mma_bf16(acc[0][nt], afr[0], bfr);
                mma_bf16(acc[1][nt], afr[1], bfr);
            }
        }
        if (kc < KE / 32 - 1) {
            *(uint4*)&a_s[buf ^ 1][grow * 40 + gco4 * 8] = av0;
            *(uint4*)&a_s[buf ^ 1][grow * 40 + gco4 * 8 + 8] = av1;
            *(uint4*)&b_s[buf ^ 1][grow * 40 + gco4 * 8] = bv0;
            *(uint4*)&b_s[buf ^ 1][grow * 40 + gco4 * 8 + 8] = bv1;
            __syncthreads();
            buf ^= 1;
        }
    }

    // epilogue: D[m][n] -> gi[row][col] + bias
#pragma unroll
    for (int mt = 0; mt < 2; mt++) {
        const int row0 = bm + mw * 32 + mt * 16 + g;
#pragma unroll
        for (int nt = 0; nt < 8; nt++) {
            const int col = bn + nw * 64 + nt * 8 + 2 * tg;
            const float bz0 = __ldg(bias + col), bz1 = __ldg(bias + col + 1);
            float2 o0 = make_float2(acc[mt][nt][0] + bz0, acc[mt][nt][1] + bz1);
            float2 o1 = make_float2(acc[mt][nt][2] + bz0, acc[mt][nt][3] + bz1);
            *(float2*)&g_gi[(size_t)row0 * G3 + col] = o0;
            *(float2*)&g_gi[(size_t)(row0 + 8) * G3 + col] = o1;
        }
    }
}

// ============================================================
// Grid-wide barrier (128 CTAs, all wave-1 resident)
// ============================================================
__device__ __forceinline__ void grid_bar(unsigned& phase) {
    __syncthreads();
    if (threadIdx.x == 0) {
        unsigned old = atomicAdd(&g_bar_count, 1u);
        if (old == NCTA - 1) {
            g_bar_count = 0;
            __threadfence();
            g_bar_phase = phase + 1;
        } else {
            while (g_bar_phase == phase) { }
        }
        __threadfence();
    }
    __syncthreads();
    phase++;
}

// ============================================================
// Persistent GRU recurrence (HMMA bf16x3).
// 128 CTAs x 256 thr. blk = cg*4+s: cg -> 96 cols of 3H, s -> K seg of 256.
// w smem [96][776]: [whi|whi|wlo]; h smem [32][776]: [hhi|hlo|hhi].
// GEMM: warps 0..5, warp = m-tile (16 cols), all 4 n-tiles (batch), K_eff=768.
// Partials to g_part; gates distributed over all 128 CTAs (1 item/thread).
// ============================================================
__global__ __launch_bounds__(NTHR, 1) void k_gru(const float* __restrict__ paddings,
                                                 const float* __restrict__ b_hh,
                                                 float* __restrict__ out,
                                                 int copies) {
    extern __shared__ char sm8[];
    __nv_bfloat16* w_s = (__nv_bfloat16*)sm8;            // [96][776]
    __nv_bfloat16* h_s = (__nv_bfloat16*)(sm8 + HS_OFF); // [32][776]
    float* tb = (float*)(sm8 + HS_OFF);                  // alias after GEMM: [32][100]

    const int tid = threadIdx.x;
    const int wid = tid >> 5, lane = tid & 31;
    const int g = lane >> 2, tg = lane & 3;
    const int blk = blockIdx.x, cg = blk >> 2, s = blk & 3;

    // ---- stage w slice once: [96 m][256 k] -> [hi|hi|lo] ----
    for (int idx = tid; idx < 96 * 256; idx += NTHR) {
        const int m = idx >> 8, k = idx & 255;
        __nv_bfloat16 hi, lo;
        split_bf16(g_wT[(size_t)(cg * 96 + m) * HH + s * 256 + k], hi, lo);
        w_s[m * WS_ROW + k] = hi;
        w_s[m * WS_ROW + 256 + k] = hi;
        w_s[m * WS_ROW + 512 + k] = lo;
    }

    // ---- gate-thread constants (all CTAs: 8 hidden dims x 32 batches) ----
    const int k0 = blk * 8 + (tid & 7);
    const int b0 = tid >> 3;
    const float bhr = b_hh[k0], bhz = b_hh[HH + k0], bhn = b_hh[2 * HH + k0];
    const float* pb[3];
#pragma unroll
    for (int g3 = 0; g3 < 3; g3++) {
        const int col = g3 * HH + k0;
        pb[g3] = g_part + (size_t)((col / 96) * 4) * 3072 + b0 * 96 + (col % 96);
    }

    // init h buffer 0
    g_h[0][b0 * HH + k0] = 0.f;
    g_hbf[0][0][b0 * HH + k0] = __float2bfloat16(0.f);
    g_hbf[0][1][b0 * HH + k0] = __float2bfloat16(0.f);
    __threadfence();

    unsigned phase = g_bar_phase;
    grid_bar(phase);

    for (int t = 0; t < TT; t++) {
        // ---- stage h seg: [32 b][256 k] hi/lo -> [hhi|hlo|hhi] ----
        const uint4* hhi = (const uint4*)g_hbf[t & 1][0];
        const uint4* hlo = (const uint4*)g_hbf[t & 1][1];
#pragma unroll 2
        for (int idx = tid; idx < 1024; idx += NTHR) {
            const int b = idx >> 5, u = idx & 31;
            const uint4 vhi = __ldcg(&hhi[b * 128 + s * 32 + u]);
            const uint4 vlo = __ldcg(&hlo[b * 128 + s * 32 + u]);
            __nv_bfloat16* hrow = h_s + b * WS_ROW + u * 8;
            *(uint4*)(hrow) = vhi;
            *(uint4*)(hrow + 256) = vlo;
            *(uint4*)(hrow + 512) = vhi;
        }
        __syncthreads();

        // ---- GEMM: warps 0..5 ----
        float acc[4][4];
        if (wid < 6) {
#pragma unroll
            for (int nt = 0; nt < 4; nt++)
#pragma unroll
                for (int p = 0; p < 4; p++) acc[nt][p] = 0.f;
            const int ar = wid * 16 + g;
#pragma unroll 4
            for (int kk = 0; kk < 48; kk++) {
                const int ka = kk * 16 + 2 * tg;
                uint32_t afr[4];
                afr[0] = *(const uint32_t*)&w_s[ar * WS_ROW + ka];
                afr[1] = *(const uint32_t*)&w_s[(ar + 8) * WS_ROW + ka];
                afr[2] = *(const uint32_t*)&w_s[ar * WS_ROW + ka + 8];
                afr[3] = *(const uint32_t*)&w_s[(ar + 8) * WS_ROW + ka + 8];
#pragma unroll
                for (int nt = 0; nt < 4; nt++) {
                    const int br = nt * 8 + g;
                    uint32_t bfr[2];
                    bfr[0] = *(const uint32_t*)&h_s[br * WS_ROW + ka];
                    bfr[1] = *(const uint32_t*)&h_s[br * WS_ROW + ka + 8];
                    mma_bf16(acc[nt], afr, bfr);
                }
            }
        }
        __syncthreads();   // all h reads done -> tb alias safe

        // ---- epilogue: D frags -> tb[b][m] ----
        if (wid < 6) {
            const int m0 = wid * 16 + g;
#pragma unroll
            for (int nt = 0; nt < 4; nt++) {
                const int bcol = nt * 8 + 2 * tg;
                tb[bcol * 100 + m0] = acc[nt][0];
                tb[(bcol + 1) * 100 + m0] = acc[nt][1];
                tb[bcol * 100 + m0 + 8] = acc[nt][2];
                tb[(bcol + 1) * 100 + m0 + 8] = acc[nt][3];
            }
        }
        __syncthreads();

        // ---- copy tb -> g_part[blk] ----
        float* gp = g_part + (size_t)blk * 3072;
#pragma unroll
        for (int i = tid; i < 768; i += NTHR) {
            const int b = i / 24, o = i - b * 24;
            *(uint4*)&gp[b * 96 + o * 4] = *(const uint4*)&tb[b * 100 + o * 4];
        }
        __threadfence();
        grid_bar(phase);

        // ---- gates (all CTAs, 1 item/thread) ----
        {
            const float* gib = g_gi + (size_t)t * BB * G3 + (size_t)b0 * G3;
            const float gir = __ldg(gib + k0);
            const float giz = __ldg(gib + HH + k0);
            const float gin = __ldg(gib + 2 * HH + k0);
            const float p = __ldg(paddings + t * BB + b0);
            float gh[3];
#pragma unroll
            for (int g3 = 0; g3 < 3; g3++)
                gh[g3] = __ldcg(pb[g3]) + __ldcg(pb[g3] + 3072)
                       + __ldcg(pb[g3] + 6144) + __ldcg(pb[g3] + 9216);
            const float hold = g_h[t & 1][b0 * HH + k0];
            const float rg = 1.f / (1.f + expf(-(gir + gh[0] + bhr)));
            const float zg = 1.f / (1.f + expf(-(giz + gh[1] + bhz)));
            const float ng = tanhf(gin + rg * (gh[2] + bhn));
            float hnew = (1.f - zg) * ng + zg * hold;
            hnew = p * hold + (1.f - p) * hnew;
            g_h[(t + 1) & 1][b0 * HH + k0] = hnew;
            __nv_bfloat16 hi, lo; split_bf16(hnew, hi, lo);
            g_hbf[(t + 1) & 1][0][b0 * HH + k0] = hi;
            g_hbf[(t + 1) & 1][1][b0 * HH + k0] = lo;
            const size_t ob = (size_t)(t * BB + b0) * HH + k0;
            for (int cp = 0; cp < copies; cp++) out[ob + (size_t)cp * OUT_COPY] = hnew;
            __threadfence();
        }
        grid_bar(phase);
    }
}

// ============================================================
extern "C" void kernel_launch(void* const* d_in, const int* in_sizes, int n_in,
                              void* d_out, int out_size) {
    const float* input    = (const float*)d_in[0];
    const float* paddings = (const float*)d_in[1];
    const float* w_ih     = (const float*)d_in[2];
    const float* w_hh     = (const float*)d_in[3];
    const float* b_ih     = (const float*)d_in[4];
    const float* b_hh     = (const float*)d_in[5];
    float* out = (float*)d_out;

    int copies = out_size / OUT_COPY;
    if (copies < 1) copies = 1;
    if (copies > 2) copies = 2;

    cudaFuncSetAttribute(k_gru, cudaFuncAttributeMaxDynamicSharedMemorySize, SMEM_GRU);

    k_transpose<<<dim3(G3 / 32, HH / 32), dim3(32, 8)>>>(w_hh);
    k_split_x<<<(TT * BB * II) / 256, 256>>>(input);
    k_split_wt<<<dim3(G3 / 32, II / 32), dim3(32, 8)>>>(w_ih);
    k_gemm_gi<<<dim3(G3 / 128, (TT * BB) / 128), 256>>>(b_ih);
    k_gru<<<NCTA, NTHR, SMEM_GRU>>>(paddings, b_hh, out, copies);
}

// round 8
// speedup vs baseline: 3.4395x; 1.0009x over previous
#include <cuda_runtime.h>
#include <cuda_bf16.h>
#include <math.h>
#include <stdint.h>

#define TT 512
#define BB 32
#define II 512
#define HH 1024
#define G3 3072
#define NCTA 128
#define NTHR 256
#define OUT_COPY (TT * BB * HH)

#define KE 1536          // K_eff for input gemm (512*3)
#define WS_ROW 776       // 768 + 8 pad (bf16 elems)
#define WS_BYTES (96 * WS_ROW * 2)          // 148992
#define HS_OFF WS_BYTES
#define SMEM_GRU (WS_BYTES + 32 * WS_ROW * 2)  // 198656

typedef unsigned long long ull;

// -------- static device scratch --------
__device__ float g_gi[(size_t)TT * BB * G3];          // gi = X@w_ih + b_ih
__device__ float g_wT[G3 * HH];                       // w_hh^T fp32 [3H][H]
__device__ __nv_bfloat16 g_xs[(size_t)TT * BB * KE];  // X split [row][hi|hi|lo]
__device__ __nv_bfloat16 g_wst[(size_t)G3 * KE];      // w_ih^T split [n][hi|lo|hi]
__device__ float g_h[2][BB * HH];                     // fp32 hidden [b][k]
__device__ __nv_bfloat16 g_hbf[2][2][BB * HH];        // bf16 hi/lo of h [b][k]
__device__ float g_part[NCTA * BB * 96];              // split-K partials [blk][b][m]
__device__ unsigned g_bar_count = 0;
__device__ volatile unsigned g_bar_phase = 0;

// bf16 mma m16n8k16: D(f32) += A(bf16,row) * B(bf16,col)
static __device__ __forceinline__ void mma_bf16(float* d, const uint32_t* a,
                                                const uint32_t* b) {
    asm volatile(
        "mma.sync.aligned.m16n8k16.row.col.f32.bf16.bf16.f32 "
        "{%0,%1,%2,%3}, {%4,%5,%6,%7}, {%8,%9}, {%0,%1,%2,%3};"
        : "+f"(d[0]), "+f"(d[1]), "+f"(d[2]), "+f"(d[3])
        : "r"(a[0]), "r"(a[1]), "r"(a[2]), "r"(a[3]), "r"(b[0]), "r"(b[1]));
}

static __device__ __forceinline__ void split_bf16(float x, __nv_bfloat16& hi,
                                                  __nv_bfloat16& lo) {
    hi = __float2bfloat16(x);
    lo = __float2bfloat16(x - __bfloat162float(hi));
}

// ============================================================
// Transpose w_hh [H][3H] -> g_wT [3H][H] (fp32)
// ============================================================
__global__ void k_transpose(const float* __restrict__ whh) {
    __shared__ float tile[32][33];
    const int col0 = blockIdx.x * 32;
    const int row0 = blockIdx.y * 32;
    const int tx = threadIdx.x, ty = threadIdx.y;
#pragma unroll
    for (int r = ty; r < 32; r += 8)
        tile[r][tx] = whh[(row0 + r) * G3 + col0 + tx];
    __syncthreads();
#pragma unroll
    for (int r = ty; r < 32; r += 8)
        g_wT[(size_t)(col0 + r) * HH + row0 + tx] = tile[tx][r];
}

// ============================================================
// Split X -> g_xs [hi | hi | lo] along K
// ============================================================
__global__ void k_split_x(const float* __restrict__ X) {
    const size_t idx = (size_t)blockIdx.x * 256 + threadIdx.x;
    const float x = X[idx];
    const size_t r = idx >> 9;          // / 512
    const int k = (int)(idx & 511);
    __nv_bfloat16 hi, lo; split_bf16(x, hi, lo);
    __nv_bfloat16* row = g_xs + r * KE;
    row[k] = hi; row[512 + k] = hi; row[1024 + k] = lo;
}

// ============================================================
// Split+transpose w_ih [512][3072] -> g_wst [3072][hi | lo | hi]
// ============================================================
__global__ void k_split_wt(const float* __restrict__ wih) {
    __shared__ float tile[32][33];
    const int col0 = blockIdx.x * 32;   // 3072 dim
    const int row0 = blockIdx.y * 32;   // 512 dim
    const int tx = threadIdx.x, ty = threadIdx.y;
#pragma unroll
    for (int r = ty; r < 32; r += 8)
        tile[r][tx] = wih[(row0 + r) * G3 + col0 + tx];
    __syncthreads();
#pragma unroll
    for (int r = ty; r < 32; r += 8) {
        const float x = tile[tx][r];
        __nv_bfloat16 hi, lo; split_bf16(x, hi, lo);
        __nv_bfloat16* row = g_wst + (size_t)(col0 + r) * KE + row0 + tx;
        row[0] = hi; row[512] = lo; row[1024] = hi;
    }
}

// ============================================================
// Input GEMM (HMMA bf16x3): gi = X@W + bias.
// M=16384, N=3072, K_eff=1536. BM=BN=128, BK=32, 256 thr (8 warps 4m x 2n).
// ============================================================
__global__ __launch_bounds__(256) void k_gemm_gi(const float* __restrict__ bias) {
    __shared__ __nv_bfloat16 a_s[2][128 * 40];
    __shared__ __nv_bfloat16 b_s[2][128 * 40];

    const int bm = blockIdx.y * 128;
    const int bn = blockIdx.x * 128;
    const int tid = threadIdx.x;
    const int wid = tid >> 5, lane = tid & 31;
    const int g = lane >> 2, tg = lane & 3;
    const int mw = wid & 3, nw = wid >> 2;   // warp tile [mw*32,+32) x [nw*64,+64)

    const int grow = tid >> 1;               // 0..127
    const int gco4 = (tid & 1) * 2;          // uint4 offset within 32-elem chunk

    const uint4* ap = (const uint4*)(g_xs + (size_t)(bm + grow) * KE);
    const uint4* bp = (const uint4*)(g_wst + (size_t)(bn + grow) * KE);

    float acc[2][8][4];
#pragma unroll
    for (int i = 0; i < 2; i++)
#pragma unroll
        for (int j = 0; j < 8; j++)
#pragma unroll
            for (int p = 0; p < 4; p++) acc[i][j][p] = 0.f;

    // prologue: chunk 0
    {
        uint4 av0 = ap[gco4], av1 = ap[gco4 + 1];
        uint4 bv0 = bp[gco4], bv1 = bp[gco4 + 1];
        *(uint4*)&a_s[0][grow * 40 + gco4 * 8] = av0;
        *(uint4*)&a_s[0][grow * 40 + gco4 * 8 + 8] = av1;
        *(uint4*)&b_s[0][grow * 40 + gco4 * 8] = bv0;
        *(uint4*)&b_s[0][grow * 40 + gco4 * 8 + 8] = bv1;
    }
    __syncthreads();

    int buf = 0;
    for (int kc = 0; kc < KE / 32; kc++) {
        uint4 av0, av1, bv0, bv1;
        if (kc < KE / 32 - 1) {
            av0 = ap[(kc + 1) * 4 + gco4]; av1 = ap[(kc + 1) * 4 + gco4 + 1];
            bv0 = bp[(kc + 1) * 4 + gco4]; bv1 = bp[(kc + 1) * 4 + gco4 + 1];
        }
#pragma unroll
        for (int kk = 0; kk < 2; kk++) {
            const int ka = kk * 16 + 2 * tg;
            uint32_t afr[2][4];
#pragma unroll
            for (int mt = 0; mt < 2; mt++) {
                const int ar = mw * 32 + mt * 16 + g;
                afr[mt][0] = *(const uint32_t*)&a_s[buf][ar * 40 + ka];
                afr[mt][1] = *(const uint32_t*)&a_s[buf][(ar + 8) * 40 + ka];
                afr[mt][2] = *(const uint32_t*)&a_s[buf][ar * 40 + ka + 8];
                afr[mt][3] = *(const uint32_t*)&a_s[buf][(ar + 8) * 40 + ka + 8];
            }
#pragma unroll
            for (int nt = 0; nt < 8; nt++) {
                const int br = nw * 64 + nt * 8 + g;
                uint32_t bfr[2];
                bfr[0] = *(const uint32_t*)&b_s[buf][br * 40 + ka];
                bfr[1] = *(const uint32_t*)&b_s[buf][br * 40 + ka + 8];
                mma_bf16(acc[0][nt], afr[0], bfr);
                mma_bf16(acc[1][nt], afr[1], bfr);
            }
        }
        if (kc < KE / 32 - 1) {
            *(uint4*)&a_s[buf ^ 1][grow * 40 + gco4 * 8] = av0;
            *(uint4*)&a_s[buf ^ 1][grow * 40 + gco4 * 8 + 8] = av1;
            *(uint4*)&b_s[buf ^ 1][grow * 40 + gco4 * 8] = bv0;
            *(uint4*)&b_s[buf ^ 1][grow * 40 + gco4 * 8 + 8] = bv1;
            __syncthreads();
            buf ^= 1;
        }
    }

    // epilogue: D[m][n] -> gi[row][col] + bias
#pragma unroll
    for (int mt = 0; mt < 2; mt++) {
        const int row0 = bm + mw * 32 + mt * 16 + g;
#pragma unroll
        for (int nt = 0; nt < 8; nt++) {
            const int col = bn + nw * 64 + nt * 8 + 2 * tg;
            const float bz0 = __ldg(bias + col), bz1 = __ldg(bias + col + 1);
            float2 o0 = make_float2(acc[mt][nt][0] + bz0, acc[mt][nt][1] + bz1);
            float2 o1 = make_float2(acc[mt][nt][2] + bz0, acc[mt][nt][3] + bz1);
            *(float2*)&g_gi[(size_t)row0 * G3 + col] = o0;
            *(float2*)&g_gi[(size_t)(row0 + 8) * G3 + col] = o1;
        }
    }
}

// ============================================================
// Grid-wide barrier (128 CTAs, all wave-1 resident)
// ============================================================
__device__ __forceinline__ void grid_bar(unsigned& phase) {
    __syncthreads();
    if (threadIdx.x == 0) {
        unsigned old = atomicAdd(&g_bar_count, 1u);
        if (old == NCTA - 1) {
            g_bar_count = 0;
            __threadfence();
            g_bar_phase = phase + 1;
        } else {
            while (g_bar_phase == phase) { }
        }
        __threadfence();
    }
    __syncthreads();
    phase++;
}

// ============================================================
// Persistent GRU recurrence (HMMA bf16x3).
// 128 CTAs x 256 thr. blk = cg*4+s: cg -> 96 cols of 3H, s -> K seg of 256.
// w smem [96][776]: [whi|whi|wlo]; h smem [32][776]: [hhi|hlo|hhi].
// GEMM: warps 0..5, warp = m-tile (16 cols), all 4 n-tiles (batch), K_eff=768.
// Partials to g_part; gates distributed over all 128 CTAs (1 item/thread).
// ============================================================
__global__ __launch_bounds__(NTHR, 1) void k_gru(const float* __restrict__ paddings,
                                                 const float* __restrict__ b_hh,
                                                 float* __restrict__ out,
                                                 int copies) {
    extern __shared__ char sm8[];
    __nv_bfloat16* w_s = (__nv_bfloat16*)sm8;            // [96][776]
    __nv_bfloat16* h_s = (__nv_bfloat16*)(sm8 + HS_OFF); // [32][776]
    float* tb = (float*)(sm8 + HS_OFF);                  // alias after GEMM: [32][100]

    const int tid = threadIdx.x;
    const int wid = tid >> 5, lane = tid & 31;
    const int g = lane >> 2, tg = lane & 3;
    const int blk = blockIdx.x, cg = blk >> 2, s = blk & 3;

    // ---- stage w slice once: [96 m][256 k] -> [hi|hi|lo] ----
    for (int idx = tid; idx < 96 * 256; idx += NTHR) {
        const int m = idx >> 8, k = idx & 255;
        __nv_bfloat16 hi, lo;
        split_bf16(g_wT[(size_t)(cg * 96 + m) * HH + s * 256 + k], hi, lo);
        w_s[m * WS_ROW + k] = hi;
        w_s[m * WS_ROW + 256 + k] = hi;
        w_s[m * WS_ROW + 512 + k] = lo;
    }

    // ---- gate-thread constants (all CTAs: 8 hidden dims x 32 batches) ----
    const int k0 = blk * 8 + (tid & 7);
    const int b0 = tid >> 3;
    const float bhr = b_hh[k0], bhz = b_hh[HH + k0], bhn = b_hh[2 * HH + k0];
    const float* pb[3];
#pragma unroll
    for (int g3 = 0; g3 < 3; g3++) {
        const int col = g3 * HH + k0;
        pb[g3] = g_part + (size_t)((col / 96) * 4) * 3072 + b0 * 96 + (col % 96);
    }

    // init h buffer 0
    g_h[0][b0 * HH + k0] = 0.f;
    g_hbf[0][0][b0 * HH + k0] = __float2bfloat16(0.f);
    g_hbf[0][1][b0 * HH + k0] = __float2bfloat16(0.f);
    __threadfence();

    unsigned phase = g_bar_phase;
    grid_bar(phase);

    for (int t = 0; t < TT; t++) {
        // ---- stage h seg: [32 b][256 k] hi/lo -> [hhi|hlo|hhi] ----
        const uint4* hhi = (const uint4*)g_hbf[t & 1][0];
        const uint4* hlo = (const uint4*)g_hbf[t & 1][1];
#pragma unroll 2
        for (int idx = tid; idx < 1024; idx += NTHR) {
            const int b = idx >> 5, u = idx & 31;
            const uint4 vhi = __ldcg(&hhi[b * 128 + s * 32 + u]);
            const uint4 vlo = __ldcg(&hlo[b * 128 + s * 32 + u]);
            __nv_bfloat16* hrow = h_s + b * WS_ROW + u * 8;
            *(uint4*)(hrow) = vhi;
            *(uint4*)(hrow + 256) = vlo;
            *(uint4*)(hrow + 512) = vhi;
        }
        __syncthreads();

        // ---- GEMM: warps 0..5 ----
        float acc[4][4];
        if (wid < 6) {
#pragma unroll
            for (int nt = 0; nt < 4; nt++)
#pragma unroll
                for (int p = 0; p < 4; p++) acc[nt][p] = 0.f;
            const int ar = wid * 16 + g;
#pragma unroll 4
            for (int kk = 0; kk < 48; kk++) {
                const int ka = kk * 16 + 2 * tg;
                uint32_t afr[4];
                afr[0] = *(const uint32_t*)&w_s[ar * WS_ROW + ka];
                afr[1] = *(const uint32_t*)&w_s[(ar + 8) * WS_ROW + ka];
                afr[2] = *(const uint32_t*)&w_s[ar * WS_ROW + ka + 8];
                afr[3] = *(const uint32_t*)&w_s[(ar + 8) * WS_ROW + ka + 8];
#pragma unroll
                for (int nt = 0; nt < 4; nt++) {
                    const int br = nt * 8 + g;
                    uint32_t bfr[2];
                    bfr[0] = *(const uint32_t*)&h_s[br * WS_ROW + ka];
                    bfr[1] = *(const uint32_t*)&h_s[br * WS_ROW + ka + 8];
                    mma_bf16(acc[nt], afr, bfr);
                }
            }
        }
        __syncthreads();   // all h reads done -> tb alias safe

        // ---- epilogue: D frags -> tb[b][m] ----
        if (wid < 6) {
            const int m0 = wid * 16 + g;
#pragma unroll
            for (int nt = 0; nt < 4; nt++) {
                const int bcol = nt * 8 + 2 * tg;
                tb[bcol * 100 + m0] = acc[nt][0];
                tb[(bcol + 1) * 100 + m0] = acc[nt][1];
                tb[bcol * 100 + m0 + 8] = acc[nt][2];
                tb[(bcol + 1) * 100 + m0 + 8] = acc[nt][3];
            }
        }
        __syncthreads();

        // ---- copy tb -> g_part[blk] ----
        float* gp = g_part + (size_t)blk * 3072;
#pragma unroll
        for (int i = tid; i < 768; i += NTHR) {
            const int b = i / 24, o = i - b * 24;
            *(uint4*)&gp[b * 96 + o * 4] = *(const uint4*)&tb[b * 100 + o * 4];
        }
        __threadfence();
        grid_bar(phase);

        // ---- gates (all CTAs, 1 item/thread) ----
        {
            const float* gib = g_gi + (size_t)t * BB * G3 + (size_t)b0 * G3;
            const float gir = __ldg(gib + k0);
            const float giz = __ldg(gib + HH + k0);
            const float gin = __ldg(gib + 2 * HH + k0);
            const float p = __ldg(paddings + t * BB + b0);
            float gh[3];
#pragma unroll
            for (int g3 = 0; g3 < 3; g3++)
                gh[g3] = __ldcg(pb[g3]) + __ldcg(pb[g3] + 3072)
                       + __ldcg(pb[g3] + 6144) + __ldcg(pb[g3] + 9216);
            const float hold = g_h[t & 1][b0 * HH + k0];
            const float rg = 1.f / (1.f + expf(-(gir + gh[0] + bhr)));
            const float zg = 1.f / (1.f + expf(-(giz + gh[1] + bhz)));
            const float ng = tanhf(gin + rg * (gh[2] + bhn));
            float hnew = (1.f - zg) * ng + zg * hold;
            hnew = p * hold + (1.f - p) * hnew;
            g_h[(t + 1) & 1][b0 * HH + k0] = hnew;
            __nv_bfloat16 hi, lo; split_bf16(hnew, hi, lo);
            g_hbf[(t + 1) & 1][0][b0 * HH + k0] = hi;
            g_hbf[(t + 1) & 1][1][b0 * HH + k0] = lo;
            const size_t ob = (size_t)(t * BB + b0) * HH + k0;
            for (int cp = 0; cp < copies; cp++) out[ob + (size_t)cp * OUT_COPY] = hnew;
            __threadfence();
        }
        grid_bar(phase);
    }
}

// ============================================================
extern "C" void kernel_launch(void* const* d_in, const int* in_sizes, int n_in,
                              void* d_out, int out_size) {
    const float* input    = (const float*)d_in[0];
    const float* paddings = (const float*)d_in[1];
    const float* w_ih     = (const float*)d_in[2];
    const float* w_hh     = (const float*)d_in[3];
    const float* b_ih     = (const float*)d_in[4];
    const float* b_hh     = (const float*)d_in[5];
    float* out = (float*)d_out;

    int copies = out_size / OUT_COPY;
    if (copies < 1) copies = 1;
    if (copies > 2) copies = 2;

    cudaFuncSetAttribute(k_gru, cudaFuncAttributeMaxDynamicSharedMemorySize, SMEM_GRU);

    k_transpose<<<dim3(G3 / 32, HH / 32), dim3(32, 8)>>>(w_hh);
    k_split_x<<<(TT * BB * II) / 256, 256>>>(input);
    k_split_wt<<<dim3(G3 / 32, II / 32), dim3(32, 8)>>>(w_ih);
    k_gemm_gi<<<dim3(G3 / 128, (TT * BB) / 128), 256>>>(b_ih);
    k_gru<<<NCTA, NTHR, SMEM_GRU>>>(paddings, b_hh, out, copies);
}